// round 8
// baseline (speedup 1.0000x reference)
#include <cuda_runtime.h>
#include <cstdint>

// LocalAttention fused kernel v4 (sm_103a).
// T[b,l,j] = dot(x[b,l,:], W[j,:]) for 18 rows (aw3:0-2, aw5:3-7, aw7:8-14, cw:15-17)
// out_k[b,l] = tanh( sigmoid(shifted-sum of T + ab_k) * T[.,dcol_k] + cb_k )
//
// v4 vs v3 (82.9us) / v2 (74.2us):
//  - 4 independent warp-pairs per block; each pair owns a 64-row x slice with
//    its own cp.async double buffer; pair-local named barriers (bar.sync id,64)
//    -> ZERO block-wide __syncthreads in the mainloop
//  - CH=4 (19 chunks): half the staging/wait/barrier events of v3
//  - staging pointers & swizzled smem offsets fully precomputed (pointer += 64B)
//  - j-split kept: 18 packed f32x2 accs/thread -> 64 regs, 4 blocks x 8 warps/SM

typedef unsigned long long ull;

#define FMA2(d, a, b) \
    asm("fma.rn.f32x2 %0, %1, %2, %0;" : "+l"(d) : "l"(a), "l"(b))

__device__ __forceinline__ float unpk_sum(ull v) {
    float lo, hi;
    asm("mov.b64 {%0, %1}, %2;" : "=f"(lo), "=f"(hi) : "l"(v));
    return lo + hi;
}

__device__ __forceinline__ float sigm(float v) {
    return 1.0f / (1.0f + __expf(-v));
}

constexpr int Lc = 500;
constexpr int Ec = 300;
constexpr int E4 = 75;             // float4 per x row
constexpr int POS = 256;           // positions per block (250 outputs + 6 halo)
constexpr int TL  = 250;
constexpr int NJ  = 18;
constexpr int JG  = 9;             // j rows per warp (j-split within pair)
constexpr int CH  = 4;             // float4 per row per chunk
constexpr int NCHUNK = 19;         // ceil(75/4); tail zero-filled
constexpr int WPITCH = 304;        // floats per weight row (300 + 4 pad)
constexpr int SLICE_W = 64 * 16;   // words per pair buffer (64 rows x 16 words)
constexpr int WS_OFF  = 8 * SLICE_W;               // 4 pairs x 2 buffers = 8192 words
constexpr int SMEM_WORDS = WS_OFF + NJ * WPITCH;   // 13664
constexpr int SMEM_BYTES = SMEM_WORDS * 4;         // 54656 B -> 4 blocks/SM

__global__ __launch_bounds__(256, 4)
void la_fused4(const float* __restrict__ x,
               const float* __restrict__ aw3, const float* __restrict__ ab3,
               const float* __restrict__ cw3, const float* __restrict__ cb3,
               const float* __restrict__ aw5, const float* __restrict__ ab5,
               const float* __restrict__ cw5, const float* __restrict__ cb5,
               const float* __restrict__ aw7, const float* __restrict__ ab7,
               const float* __restrict__ cw7, const float* __restrict__ cb7,
               float* __restrict__ out, int Ltot)
{
    extern __shared__ float sm[];
    float* ws = sm + WS_OFF;

    const int tid  = threadIdx.x;
    const int b    = blockIdx.y;
    const int tile = blockIdx.x;
    const int l_base = tile * TL - 3;
    const float* xrow0 = x + (size_t)b * Lc * Ec;

    const int lane = tid & 31;
    const int wid  = tid >> 5;
    const int p    = wid >> 1;         // pair id 0..3
    const int jbase = (wid & 1) * JG;  // 0 or 9
    const int pt   = tid & 63;         // thread index within pair

    uint32_t sbase;
    asm("{ .reg .u64 t; cvta.to.shared.u64 t, %1; cvt.u32.u64 %0, t; }"
        : "=r"(sbase) : "l"(sm));
    const uint32_t buf0 = sbase + (uint32_t)(p * 2) * SLICE_W * 4;
    const uint32_t buf1 = buf0 + SLICE_W * 4;

    // ---- per-thread staging state: 4 (row,col) 16B chunks per stage call ----
    const float* gsrc[4];
    uint32_t     soff[4];     // byte offset within a pair buffer (swizzled)
    int          vld[4];      // row-valid (l in range)
    int          cl3[4];      // col==3 flag (tail chunk masking)
    #pragma unroll
    for (int i = 0; i < 4; ++i) {
        int f  = pt + 64 * i;
        int r  = f >> 2;              // local row 0..63
        int cl = f & 3;               // col 0..3
        int l  = l_base + p * 64 + r;
        int v  = (l >= 0) && (l < Lc);
        gsrc[i] = xrow0 + (v ? ((size_t)l * Ec + cl * 4) : 0);
        soff[i] = (uint32_t)(r * 16 + ((cl ^ ((r >> 1) & 3)) << 2)) * 4;
        vld[i]  = v;
        cl3[i]  = (cl == 3);
    }

    // stage chunk c into buffer (c&1); always commits exactly one group
    auto stage = [&](int c) {
        if (c < NCHUNK) {
            const uint32_t base = (c & 1) ? buf1 : buf0;
            const int tail = (c == NCHUNK - 1);   // eg = 72..75; col 3 -> eg 75 invalid
            #pragma unroll
            for (int i = 0; i < 4; ++i) {
                int sz = (vld[i] && !(tail && cl3[i])) ? 16 : 0;
                asm volatile("cp.async.cg.shared.global [%0], [%1], 16, %2;"
                             :: "r"(base + soff[i]), "l"(gsrc[i]), "r"(sz));
                gsrc[i] += CH * 4;     // advance 64B to next chunk
            }
        }
        asm volatile("cp.async.commit_group;");
    };

    // ---- kick off DMA before anything else ----
    stage(0);
    stage(1);

    // ---- weights -> shared (one-time, whole block) ----
    for (int i = tid; i < 3 * Ec; i += 256) ws[(     i / Ec) * WPITCH + (i % Ec)] = aw3[i];
    for (int i = tid; i < 5 * Ec; i += 256) ws[(3 +  i / Ec) * WPITCH + (i % Ec)] = aw5[i];
    for (int i = tid; i < 7 * Ec; i += 256) ws[(8 +  i / Ec) * WPITCH + (i % Ec)] = aw7[i];
    for (int i = tid; i < Ec; i += 256) {
        ws[15 * WPITCH + i] = cw3[i];
        ws[16 * WPITCH + i] = cw5[i];
        ws[17 * WPITCH + i] = cw7[i];
    }
    if (tid < NJ * 4) ws[(tid >> 2) * WPITCH + 300 + (tid & 3)] = 0.0f;  // pad col
    __syncthreads();   // weights visible to all; stage(0)/(1) still in flight

    asm volatile("cp.async.wait_group 1;" ::: "memory");  // stage(0) complete

    // positions owned by this thread: local rows lane and lane+32 of pair slice
    const int rA = lane, rB = lane + 32;
    const int sw = (lane >> 1) & 3;           // same swizzle phase for rA and rB
    const float* pairbuf[2] = { sm + (size_t)p * 2 * SLICE_W,
                                sm + (size_t)(p * 2 + 1) * SLICE_W };
    const int barid = p + 1;

    ull accA[JG], accB[JG];
    #pragma unroll
    for (int j = 0; j < JG; ++j) { accA[j] = 0ull; accB[j] = 0ull; }

    asm volatile("bar.sync %0, 64;" :: "r"(barid) : "memory");

    for (int c = 0; c < NCHUNK; ++c) {
        const float* xb = pairbuf[c & 1];
        const float* pA = xb + rA * 16;
        const float* pB = xb + rB * 16;
        const float* wc = ws + jbase * WPITCH + c * (CH * 4);

        #pragma unroll
        for (int e = 0; e < CH; ++e) {
            const int sl = ((e ^ sw) << 2);
            ulonglong2 xa = *(const ulonglong2*)(pA + sl);
            ulonglong2 xv = *(const ulonglong2*)(pB + sl);
            #pragma unroll
            for (int j = 0; j < JG; ++j) {
                ulonglong2 wv = *(const ulonglong2*)(wc + j * WPITCH + e * 4);
                FMA2(accA[j], xa.x, wv.x);
                FMA2(accA[j], xa.y, wv.y);
                FMA2(accB[j], xv.x, wv.x);
                FMA2(accB[j], xv.y, wv.y);
            }
        }

        // pair done reading buf (c&1) -> safe to overwrite
        asm volatile("bar.sync %0, 64;" :: "r"(barid) : "memory");
        stage(c + 2);
        asm volatile("cp.async.wait_group 1;" ::: "memory");  // stage(c+1) done
        asm volatile("bar.sync %0, 64;" :: "r"(barid) : "memory");
    }

    // ---- all pairs done; alias T over the (dead) x slices ----
    __syncthreads();
    float* Tsh = sm;                       // 256*19 = 4864 words < 8192
    const int posA = p * 64 + rA;
    const int posB = p * 64 + rB;
    #pragma unroll
    for (int j = 0; j < JG; ++j) {
        Tsh[posA * 19 + jbase + j] = unpk_sum(accA[j]);
        Tsh[posB * 19 + jbase + j] = unpk_sum(accB[j]);
    }
    __syncthreads();

    // ---- epilogue: shifted sums + sigmoid gate + tanh ----
    const int pos = tid;
    if (pos >= 3 && pos <= 252) {
        const float* T0 = &Tsh[pos * 19];
        float s3 = Tsh[(pos - 1) * 19 + 0] + T0[1] + Tsh[(pos + 1) * 19 + 2];
        float s5 = 0.f;
        #pragma unroll
        for (int j = 0; j < 5; ++j) s5 += Tsh[(pos - 2 + j) * 19 + 3 + j];
        float s7 = 0.f;
        #pragma unroll
        for (int j = 0; j < 7; ++j) s7 += Tsh[(pos - 3 + j) * 19 + 8 + j];

        float o3 = tanhf(sigm(s3 + ab3[0]) * T0[15] + cb3[0]);
        float o5 = tanhf(sigm(s5 + ab5[0]) * T0[16] + cb5[0]);
        float o7 = tanhf(sigm(s7 + ab7[0]) * T0[17] + cb7[0]);

        const int l_out = l_base + pos;
        const size_t oi = (size_t)b * Lc + l_out;
        out[oi]                    = o3;
        out[(size_t)Ltot + oi]     = o5;
        out[2 * (size_t)Ltot + oi] = o7;
    }
}

extern "C" void kernel_launch(void* const* d_in, const int* in_sizes, int n_in,
                              void* d_out, int out_size) {
    const float* x   = (const float*)d_in[0];
    const float* aw3 = (const float*)d_in[1];
    const float* ab3 = (const float*)d_in[2];
    const float* cw3 = (const float*)d_in[3];
    const float* cb3 = (const float*)d_in[4];
    const float* aw5 = (const float*)d_in[5];
    const float* ab5 = (const float*)d_in[6];
    const float* cw5 = (const float*)d_in[7];
    const float* cb5 = (const float*)d_in[8];
    const float* aw7 = (const float*)d_in[9];
    const float* ab7 = (const float*)d_in[10];
    const float* cw7 = (const float*)d_in[11];
    const float* cb7 = (const float*)d_in[12];
    float* out = (float*)d_out;

    const int Bn   = in_sizes[0] / (Lc * Ec);   // 256
    const int Ltot = Bn * Lc;

    cudaFuncSetAttribute(la_fused4, cudaFuncAttributeMaxDynamicSharedMemorySize,
                         SMEM_BYTES);

    dim3 grid(2, Bn);
    dim3 block(256);
    la_fused4<<<grid, block, SMEM_BYTES>>>(x,
                                           aw3, ab3, cw3, cb3,
                                           aw5, ab5, cw5, cb5,
                                           aw7, ab7, cw7, cb7,
                                           out, Ltot);
}